// round 1
// baseline (speedup 1.0000x reference)
#include <cuda_runtime.h>

#define NN   50000
#define EE   800000
#define DIN  64
#define DH   128
#define DOUT 64

// ---------------- scratch (static device globals; no allocation) ----------------
__device__ int   g_is64;
__device__ int   g_cnt[NN];
__device__ int   g_offs[NN + 1];
__device__ int   g_cursor[NN];
__device__ int   g_bsum[64];
__device__ int   g_boff[64];
__device__ int   g_src[EE];
__device__ float g_agg1[(size_t)NN * DIN];
__device__ float g_pre1[(size_t)NN * DH];
__device__ float g_h   [(size_t)NN * DH];
__device__ float g_agg2[(size_t)NN * DH];
__device__ float g_pre2[(size_t)NN * DOUT];

// ---------------- edge index helpers (int32 vs int64 detection) ----------------
__global__ void k_detect(const int* __restrict__ ei32) {
    // If edge_index is int64 (values < 2^31, little endian), every odd 32-bit
    // word is zero. If int32, the odd words are random values in [0, 50000)
    // (P(all 128 are zero) ~ 0).
    __shared__ int nz;
    if (threadIdx.x == 0) nz = 0;
    __syncthreads();
    for (int i = threadIdx.x; i < 128; i += blockDim.x)
        if (ei32[2 * i + 1] != 0) atomicAdd(&nz, 1);
    __syncthreads();
    if (threadIdx.x == 0) g_is64 = (nz == 0) ? 1 : 0;
}

__device__ __forceinline__ int edge_val(const void* ei, int idx) {
    if (g_is64) return (int)((const long long*)ei)[idx];
    return ((const int*)ei)[idx];
}

// ---------------- CSR build ----------------
__global__ void k_zero_cnt() {
    int i = blockIdx.x * blockDim.x + threadIdx.x;
    if (i < NN) g_cnt[i] = 0;
}

__global__ void k_hist(const void* __restrict__ ei) {
    int e = blockIdx.x * blockDim.x + threadIdx.x;
    if (e < EE) {
        int d = edge_val(ei, EE + e);
        atomicAdd(&g_cnt[d], 1);
    }
}

__global__ void k_scan1() {
    __shared__ int s[1024];
    int t = threadIdx.x;
    int gid = blockIdx.x * 1024 + t;
    int v = (gid < NN) ? g_cnt[gid] : 0;
    s[t] = v;
    __syncthreads();
    for (int o = 1; o < 1024; o <<= 1) {
        int x = (t >= o) ? s[t - o] : 0;
        __syncthreads();
        s[t] += x;
        __syncthreads();
    }
    if (gid < NN) g_offs[gid + 1] = s[t];       // partial inclusive prefix
    if (t == 1023) g_bsum[blockIdx.x] = s[1023];
}

__global__ void k_scan2(int nb) {
    __shared__ int s[64];
    int t = threadIdx.x;
    int v = (t < nb) ? g_bsum[t] : 0;
    s[t] = v;
    __syncthreads();
    for (int o = 1; o < 64; o <<= 1) {
        int x = (t >= o) ? s[t - o] : 0;
        __syncthreads();
        s[t] += x;
        __syncthreads();
    }
    g_boff[t] = s[t] - v;   // exclusive prefix of block sums
}

__global__ void k_scan3() {
    int t = threadIdx.x;
    int gid = blockIdx.x * 1024 + t;
    if (gid < NN) {
        int f = g_offs[gid + 1] + g_boff[blockIdx.x];
        g_offs[gid + 1] = f;
        g_cursor[gid] = f - g_cnt[gid];   // exclusive prefix
        if (gid == 0) g_offs[0] = 0;
    }
}

__global__ void k_scatter(const void* __restrict__ ei) {
    int e = blockIdx.x * blockDim.x + threadIdx.x;
    if (e < EE) {
        int s = edge_val(ei, e);
        int d = edge_val(ei, EE + e);
        int pos = atomicAdd(&g_cursor[d], 1);
        g_src[pos] = s;
    }
}

// ---------------- gather aggregation (segment_sum via CSR) ----------------
template <int D>
__global__ void k_agg(const float* __restrict__ feat, float* __restrict__ out) {
    int w = (blockIdx.x * blockDim.x + threadIdx.x) >> 5;
    if (w >= NN) return;
    int lane = threadIdx.x & 31;
    int s = g_offs[w], e = g_offs[w + 1];
    if (D == 64) {
        float2 acc = make_float2(0.f, 0.f);
        for (int i = s; i < e; i++) {
            int sr = g_src[i];
            float2 v = *reinterpret_cast<const float2*>(feat + (size_t)sr * 64 + 2 * lane);
            acc.x += v.x; acc.y += v.y;
        }
        *reinterpret_cast<float2*>(out + (size_t)w * 64 + 2 * lane) = acc;
    } else {
        float4 acc = make_float4(0.f, 0.f, 0.f, 0.f);
        for (int i = s; i < e; i++) {
            int sr = g_src[i];
            float4 v = *reinterpret_cast<const float4*>(feat + (size_t)sr * 128 + 4 * lane);
            acc.x += v.x; acc.y += v.y; acc.z += v.z; acc.w += v.w;
        }
        *reinterpret_cast<float4*>(out + (size_t)w * 128 + 4 * lane) = acc;
    }
}

// ---------------- fused dual GEMM: out = A1@Wl + A2@Wr + b ----------------
// A = [A1 | A2] (K = K1+K2), W = [Wl ; Wr] fully resident in smem.
template <int K1, int K2, int NOUT, int BM>
__global__ __launch_bounds__(256)
void k_gemm(const float* __restrict__ A1, const float* __restrict__ A2,
            const float* __restrict__ Wl, const float* __restrict__ Wr,
            const float* __restrict__ bias, float* __restrict__ out) {
    constexpr int K   = K1 + K2;
    constexpr int TX  = NOUT / 4;       // threads along output cols (float4)
    constexpr int TY  = 256 / TX;       // threads along nodes
    constexpr int MPT = BM / TY;        // nodes per thread
    extern __shared__ float sm[];
    float* Ws = sm;                     // [K][NOUT]
    float* As = sm + K * NOUT;          // [BM][K]

    int tid = threadIdx.x;

    // load concatenated weight matrix once per block
    for (int v = tid; v < (K * NOUT) / 4; v += 256) {
        int idx = v * 4;
        float4 val;
        if (idx < K1 * NOUT) val = *reinterpret_cast<const float4*>(Wl + idx);
        else                 val = *reinterpret_cast<const float4*>(Wr + (idx - K1 * NOUT));
        *reinterpret_cast<float4*>(Ws + idx) = val;
    }

    int tx = tid % TX, ty = tid / TX;
    float4 bv = *reinterpret_cast<const float4*>(bias + 4 * tx);

    int numTiles = (NN + BM - 1) / BM;
    for (int tile = blockIdx.x; tile < numTiles; tile += gridDim.x) {
        __syncthreads();   // previous iteration's As reads done
        int base = tile * BM;
        for (int v = tid; v < (BM * K) / 4; v += 256) {
            int idx = v * 4;
            int row = idx / K, col = idx % K;
            int node = base + row;
            float4 val = make_float4(0.f, 0.f, 0.f, 0.f);
            if (node < NN) {
                if (col < K1) val = *reinterpret_cast<const float4*>(A1 + (size_t)node * K1 + col);
                else          val = *reinterpret_cast<const float4*>(A2 + (size_t)node * K2 + (col - K1));
            }
            *reinterpret_cast<float4*>(As + idx) = val;
        }
        __syncthreads();

        float4 acc[MPT];
#pragma unroll
        for (int m = 0; m < MPT; m++) acc[m] = make_float4(0.f, 0.f, 0.f, 0.f);

#pragma unroll 4
        for (int k = 0; k < K; k++) {
            float4 w = *reinterpret_cast<const float4*>(Ws + k * NOUT + 4 * tx);
#pragma unroll
            for (int m = 0; m < MPT; m++) {
                float a = As[(ty * MPT + m) * K + k];
                acc[m].x += a * w.x;
                acc[m].y += a * w.y;
                acc[m].z += a * w.z;
                acc[m].w += a * w.w;
            }
        }

#pragma unroll
        for (int m = 0; m < MPT; m++) {
            int node = base + ty * MPT + m;
            if (node < NN) {
                float4 o = make_float4(acc[m].x + bv.x, acc[m].y + bv.y,
                                       acc[m].z + bv.z, acc[m].w + bv.w);
                *reinterpret_cast<float4*>(out + (size_t)node * NOUT + 4 * tx) = o;
            }
        }
    }
}

// ---------------- row L2-normalize + eval BN (+ReLU) ----------------
template <int D, bool RELU>
__global__ void k_norm(const float* __restrict__ in,
                       const float* __restrict__ gam, const float* __restrict__ bet,
                       const float* __restrict__ rm,  const float* __restrict__ rv,
                       float* __restrict__ out) {
    int w = (blockIdx.x * blockDim.x + threadIdx.x) >> 5;
    if (w >= NN) return;
    int lane = threadIdx.x & 31;
    if (D == 128) {
        float4 v = *reinterpret_cast<const float4*>(in + (size_t)w * 128 + 4 * lane);
        float ss = v.x * v.x + v.y * v.y + v.z * v.z + v.w * v.w;
#pragma unroll
        for (int o = 16; o > 0; o >>= 1) ss += __shfl_xor_sync(0xffffffffu, ss, o);
        float scale = 1.0f / fmaxf(sqrtf(ss), 1e-12f);
        float4 G  = *reinterpret_cast<const float4*>(gam + 4 * lane);
        float4 B  = *reinterpret_cast<const float4*>(bet + 4 * lane);
        float4 RM = *reinterpret_cast<const float4*>(rm  + 4 * lane);
        float4 RV = *reinterpret_cast<const float4*>(rv  + 4 * lane);
        float4 o;
        o.x = G.x * (v.x * scale - RM.x) * rsqrtf(RV.x + 1e-5f) + B.x;
        o.y = G.y * (v.y * scale - RM.y) * rsqrtf(RV.y + 1e-5f) + B.y;
        o.z = G.z * (v.z * scale - RM.z) * rsqrtf(RV.z + 1e-5f) + B.z;
        o.w = G.w * (v.w * scale - RM.w) * rsqrtf(RV.w + 1e-5f) + B.w;
        if (RELU) {
            o.x = fmaxf(o.x, 0.f); o.y = fmaxf(o.y, 0.f);
            o.z = fmaxf(o.z, 0.f); o.w = fmaxf(o.w, 0.f);
        }
        *reinterpret_cast<float4*>(out + (size_t)w * 128 + 4 * lane) = o;
    } else {
        float2 v = *reinterpret_cast<const float2*>(in + (size_t)w * 64 + 2 * lane);
        float ss = v.x * v.x + v.y * v.y;
#pragma unroll
        for (int o = 16; o > 0; o >>= 1) ss += __shfl_xor_sync(0xffffffffu, ss, o);
        float scale = 1.0f / fmaxf(sqrtf(ss), 1e-12f);
        float2 G  = *reinterpret_cast<const float2*>(gam + 2 * lane);
        float2 B  = *reinterpret_cast<const float2*>(bet + 2 * lane);
        float2 RM = *reinterpret_cast<const float2*>(rm  + 2 * lane);
        float2 RV = *reinterpret_cast<const float2*>(rv  + 2 * lane);
        float2 o;
        o.x = G.x * (v.x * scale - RM.x) * rsqrtf(RV.x + 1e-5f) + B.x;
        o.y = G.y * (v.y * scale - RM.y) * rsqrtf(RV.y + 1e-5f) + B.y;
        if (RELU) { o.x = fmaxf(o.x, 0.f); o.y = fmaxf(o.y, 0.f); }
        *reinterpret_cast<float2*>(out + (size_t)w * 64 + 2 * lane) = o;
    }
}

// ---------------- launch ----------------
extern "C" void kernel_launch(void* const* d_in, const int* in_sizes, int n_in,
                              void* d_out, int out_size) {
    const float* x    = (const float*)d_in[0];
    const void*  ei   = d_in[1];
    const float* W1l  = (const float*)d_in[2];
    const float* b1   = (const float*)d_in[3];
    const float* W1r  = (const float*)d_in[4];
    const float* gam1 = (const float*)d_in[5];
    const float* bet1 = (const float*)d_in[6];
    const float* rm1  = (const float*)d_in[7];
    const float* rv1  = (const float*)d_in[8];
    const float* W2l  = (const float*)d_in[9];
    const float* b2   = (const float*)d_in[10];
    const float* W2r  = (const float*)d_in[11];
    const float* gam2 = (const float*)d_in[12];
    const float* bet2 = (const float*)d_in[13];
    const float* rm2  = (const float*)d_in[14];
    const float* rv2  = (const float*)d_in[15];
    float* out = (float*)d_out;

    float *agg1, *pre1, *h, *agg2, *pre2;
    cudaGetSymbolAddress((void**)&agg1, g_agg1);
    cudaGetSymbolAddress((void**)&pre1, g_pre1);
    cudaGetSymbolAddress((void**)&h,    g_h);
    cudaGetSymbolAddress((void**)&agg2, g_agg2);
    cudaGetSymbolAddress((void**)&pre2, g_pre2);

    constexpr int SMEM1 = (128 * 128 + 64 * 128) * 4;   // 96 KB
    constexpr int SMEM2 = (256 * 64 + 32 * 256) * 4;    // 96 KB
    cudaFuncSetAttribute(k_gemm<64, 64, 128, 64>,
                         cudaFuncAttributeMaxDynamicSharedMemorySize, SMEM1);
    cudaFuncSetAttribute(k_gemm<128, 128, 64, 32>,
                         cudaFuncAttributeMaxDynamicSharedMemorySize, SMEM2);

    const int NB = (NN + 1023) / 1024;                  // 49
    const int EB = (EE + 255) / 256;                    // edge blocks
    const int WARP_BLOCKS = (NN * 32 + 255) / 256;      // warp-per-node blocks

    // CSR build
    k_detect<<<1, 128>>>((const int*)ei);
    k_zero_cnt<<<(NN + 255) / 256, 256>>>();
    k_hist<<<EB, 256>>>(ei);
    k_scan1<<<NB, 1024>>>();
    k_scan2<<<1, 64>>>(NB);
    k_scan3<<<NB, 1024>>>();
    k_scatter<<<EB, 256>>>(ei);

    // layer 1
    k_agg<64><<<WARP_BLOCKS, 256>>>(x, agg1);
    k_gemm<64, 64, 128, 64><<<296, 256, SMEM1>>>(agg1, x, W1l, W1r, b1, pre1);
    k_norm<128, true><<<WARP_BLOCKS, 256>>>(pre1, gam1, bet1, rm1, rv1, h);

    // layer 2
    k_agg<128><<<WARP_BLOCKS, 256>>>(h, agg2);
    k_gemm<128, 128, 64, 32><<<296, 256, SMEM2>>>(agg2, h, W2l, W2r, b2, pre2);
    k_norm<64, false><<<WARP_BLOCKS, 256>>>(pre2, gam2, bet2, rm2, rv2, out);
}

// round 2
// speedup vs baseline: 1.2391x; 1.2391x over previous
#include <cuda_runtime.h>

#define NN   50000
#define EE   800000
#define DIN  64
#define DH   128
#define DOUT 64

// ---------------- scratch (static device globals; no allocation) ----------------
__device__ int   g_is64;
__device__ int   g_cnt[NN];
__device__ int   g_offs[NN + 1];
__device__ int   g_cursor[NN];
__device__ int   g_bsum[64];
__device__ int   g_boff[64];
__device__ int   g_src[EE];
__device__ float g_agg1[(size_t)NN * DIN];
__device__ float g_h   [(size_t)NN * DH];
__device__ float g_yz  [(size_t)NN * DH];

// ---------------- edge index helpers (int32 vs int64 detection) ----------------
__global__ void k_detect(const int* __restrict__ ei32) {
    __shared__ int nz;
    if (threadIdx.x == 0) nz = 0;
    __syncthreads();
    for (int i = threadIdx.x; i < 128; i += blockDim.x)
        if (ei32[2 * i + 1] != 0) atomicAdd(&nz, 1);
    __syncthreads();
    if (threadIdx.x == 0) g_is64 = (nz == 0) ? 1 : 0;
}

__device__ __forceinline__ int edge_val(const void* ei, int idx) {
    if (g_is64) return (int)((const long long*)ei)[idx];
    return ((const int*)ei)[idx];
}

// ---------------- CSR build ----------------
__global__ void k_zero_cnt() {
    int i = blockIdx.x * blockDim.x + threadIdx.x;
    if (i < NN) g_cnt[i] = 0;
}

__global__ void k_hist(const void* __restrict__ ei) {
    int e = blockIdx.x * blockDim.x + threadIdx.x;
    if (e < EE) {
        int d = edge_val(ei, EE + e);
        atomicAdd(&g_cnt[d], 1);
    }
}

__global__ void k_scan1() {
    __shared__ int s[1024];
    int t = threadIdx.x;
    int gid = blockIdx.x * 1024 + t;
    int v = (gid < NN) ? g_cnt[gid] : 0;
    s[t] = v;
    __syncthreads();
    for (int o = 1; o < 1024; o <<= 1) {
        int x = (t >= o) ? s[t - o] : 0;
        __syncthreads();
        s[t] += x;
        __syncthreads();
    }
    if (gid < NN) g_offs[gid + 1] = s[t];
    if (t == 1023) g_bsum[blockIdx.x] = s[1023];
}

__global__ void k_scan2(int nb) {
    __shared__ int s[64];
    int t = threadIdx.x;
    int v = (t < nb) ? g_bsum[t] : 0;
    s[t] = v;
    __syncthreads();
    for (int o = 1; o < 64; o <<= 1) {
        int x = (t >= o) ? s[t - o] : 0;
        __syncthreads();
        s[t] += x;
        __syncthreads();
    }
    g_boff[t] = s[t] - v;
}

__global__ void k_scan3() {
    int t = threadIdx.x;
    int gid = blockIdx.x * 1024 + t;
    if (gid < NN) {
        int f = g_offs[gid + 1] + g_boff[blockIdx.x];
        g_offs[gid + 1] = f;
        g_cursor[gid] = f - g_cnt[gid];
        if (gid == 0) g_offs[0] = 0;
    }
}

__global__ void k_scatter(const void* __restrict__ ei) {
    int e = blockIdx.x * blockDim.x + threadIdx.x;
    if (e < EE) {
        int s = edge_val(ei, e);
        int d = edge_val(ei, EE + e);
        int pos = atomicAdd(&g_cursor[d], 1);
        g_src[pos] = s;
    }
}

// ---------------- layer-1 aggregation: agg1 = segsum(x[src]), 64-d ----------------
__global__ void k_agg1(const float* __restrict__ feat, float* __restrict__ out) {
    int w = (blockIdx.x * blockDim.x + threadIdx.x) >> 5;
    if (w >= NN) return;
    int lane = threadIdx.x & 31;
    int s = g_offs[w], e = g_offs[w + 1];
    float2 a0 = make_float2(0.f, 0.f), a1 = make_float2(0.f, 0.f);
    float2 a2 = make_float2(0.f, 0.f), a3 = make_float2(0.f, 0.f);
    int i = s;
    for (; i + 4 <= e; i += 4) {
        int s0 = __ldg(&g_src[i]),     s1 = __ldg(&g_src[i + 1]);
        int s2 = __ldg(&g_src[i + 2]), s3 = __ldg(&g_src[i + 3]);
        float2 v0 = *reinterpret_cast<const float2*>(feat + (size_t)s0 * 64 + 2 * lane);
        float2 v1 = *reinterpret_cast<const float2*>(feat + (size_t)s1 * 64 + 2 * lane);
        float2 v2 = *reinterpret_cast<const float2*>(feat + (size_t)s2 * 64 + 2 * lane);
        float2 v3 = *reinterpret_cast<const float2*>(feat + (size_t)s3 * 64 + 2 * lane);
        a0.x += v0.x; a0.y += v0.y;  a1.x += v1.x; a1.y += v1.y;
        a2.x += v2.x; a2.y += v2.y;  a3.x += v3.x; a3.y += v3.y;
    }
    for (; i < e; i++) {
        int sr = __ldg(&g_src[i]);
        float2 v = *reinterpret_cast<const float2*>(feat + (size_t)sr * 64 + 2 * lane);
        a0.x += v.x; a0.y += v.y;
    }
    float2 acc = make_float2((a0.x + a1.x) + (a2.x + a3.x),
                             (a0.y + a1.y) + (a2.y + a3.y));
    *reinterpret_cast<float2*>(out + (size_t)w * 64 + 2 * lane) = acc;
}

// ---------------- layer-1 fused GEMM + L2norm + BN + ReLU ----------------
// h = relu(bn(l2norm([agg1|x] @ [W1l;W1r] + b1)))
// K=128 (64+64), NOUT=128, BM=64. TX=32 (row fully inside one warp), TY=8, MPT=8.
__global__ __launch_bounds__(256)
void k_gemm1(const float* __restrict__ A1, const float* __restrict__ A2,
             const float* __restrict__ Wl, const float* __restrict__ Wr,
             const float* __restrict__ bias,
             const float* __restrict__ gam, const float* __restrict__ bet,
             const float* __restrict__ rm,  const float* __restrict__ rv,
             float* __restrict__ out) {
    constexpr int K = 128, NOUT = 128, BM = 64;
    constexpr int TX = NOUT / 4, TY = 256 / TX, MPT = BM / TY;
    extern __shared__ float sm[];
    float* Ws = sm;                 // [K][NOUT]
    float* As = sm + K * NOUT;      // [BM][K]
    int tid = threadIdx.x;

    for (int v = tid; v < (K * NOUT) / 4; v += 256) {
        int idx = v * 4;
        float4 val;
        if (idx < 64 * NOUT) val = *reinterpret_cast<const float4*>(Wl + idx);
        else                 val = *reinterpret_cast<const float4*>(Wr + (idx - 64 * NOUT));
        *reinterpret_cast<float4*>(Ws + idx) = val;
    }

    int tx = tid % TX, ty = tid / TX;
    float4 bv = *reinterpret_cast<const float4*>(bias + 4 * tx);
    float4 G  = *reinterpret_cast<const float4*>(gam  + 4 * tx);
    float4 B  = *reinterpret_cast<const float4*>(bet  + 4 * tx);
    float4 RM = *reinterpret_cast<const float4*>(rm   + 4 * tx);
    float4 RV = *reinterpret_cast<const float4*>(rv   + 4 * tx);
    float4 IS;
    IS.x = rsqrtf(RV.x + 1e-5f); IS.y = rsqrtf(RV.y + 1e-5f);
    IS.z = rsqrtf(RV.z + 1e-5f); IS.w = rsqrtf(RV.w + 1e-5f);

    int numTiles = (NN + BM - 1) / BM;
    for (int tile = blockIdx.x; tile < numTiles; tile += gridDim.x) {
        __syncthreads();
        int base = tile * BM;
        for (int v = tid; v < (BM * K) / 4; v += 256) {
            int idx = v * 4;
            int row = idx / K, col = idx % K;
            int node = base + row;
            float4 val = make_float4(0.f, 0.f, 0.f, 0.f);
            if (node < NN) {
                if (col < 64) val = *reinterpret_cast<const float4*>(A1 + (size_t)node * 64 + col);
                else          val = *reinterpret_cast<const float4*>(A2 + (size_t)node * 64 + (col - 64));
            }
            *reinterpret_cast<float4*>(As + idx) = val;
        }
        __syncthreads();

        float4 acc[MPT];
#pragma unroll
        for (int m = 0; m < MPT; m++) acc[m] = make_float4(0.f, 0.f, 0.f, 0.f);
#pragma unroll 4
        for (int k = 0; k < K; k++) {
            float4 w = *reinterpret_cast<const float4*>(Ws + k * NOUT + 4 * tx);
#pragma unroll
            for (int m = 0; m < MPT; m++) {
                float a = As[(ty * MPT + m) * K + k];
                acc[m].x += a * w.x; acc[m].y += a * w.y;
                acc[m].z += a * w.z; acc[m].w += a * w.w;
            }
        }

#pragma unroll
        for (int m = 0; m < MPT; m++) {
            float4 v = acc[m];
            v.x += bv.x; v.y += bv.y; v.z += bv.z; v.w += bv.w;
            float ss = v.x * v.x + v.y * v.y + v.z * v.z + v.w * v.w;
#pragma unroll
            for (int o = 16; o > 0; o >>= 1) ss += __shfl_xor_sync(0xffffffffu, ss, o);
            float scale = 1.0f / fmaxf(sqrtf(ss), 1e-12f);
            int node = base + ty * MPT + m;
            if (node < NN) {
                float4 o;
                o.x = fmaxf(G.x * (v.x * scale - RM.x) * IS.x + B.x, 0.f);
                o.y = fmaxf(G.y * (v.y * scale - RM.y) * IS.y + B.y, 0.f);
                o.z = fmaxf(G.z * (v.z * scale - RM.z) * IS.z + B.z, 0.f);
                o.w = fmaxf(G.w * (v.w * scale - RM.w) * IS.w + B.w, 0.f);
                *reinterpret_cast<float4*>(out + (size_t)node * NOUT + 4 * tx) = o;
            }
        }
    }
}

// ---------------- layer-2 projection GEMM: yz = h @ [W2l | W2r], +b2 on right ----
// y (cols 0..63) feeds the gather; z (cols 64..127) = h@W2r + b2.
__global__ __launch_bounds__(256)
void k_gemm2(const float* __restrict__ A,
             const float* __restrict__ Wl, const float* __restrict__ Wr,
             const float* __restrict__ bias, float* __restrict__ out) {
    constexpr int K = 128, NOUT = 128, BM = 64;
    constexpr int TX = NOUT / 4, TY = 256 / TX, MPT = BM / TY;
    extern __shared__ float sm[];
    float* Ws = sm;
    float* As = sm + K * NOUT;
    int tid = threadIdx.x;

    // Ws[k][n] : n<64 -> W2l[k][n] ; n>=64 -> W2r[k][n-64]
    for (int v = tid; v < (K * NOUT) / 4; v += 256) {
        int idx = v * 4;
        int k = idx / NOUT, n = idx % NOUT;
        float4 val;
        if (n < 64) val = *reinterpret_cast<const float4*>(Wl + k * 64 + n);
        else        val = *reinterpret_cast<const float4*>(Wr + k * 64 + (n - 64));
        *reinterpret_cast<float4*>(Ws + idx) = val;
    }

    int tx = tid % TX, ty = tid / TX;
    float4 bv = make_float4(0.f, 0.f, 0.f, 0.f);
    if (4 * tx >= 64) bv = *reinterpret_cast<const float4*>(bias + 4 * tx - 64);

    int numTiles = (NN + BM - 1) / BM;
    for (int tile = blockIdx.x; tile < numTiles; tile += gridDim.x) {
        __syncthreads();
        int base = tile * BM;
        for (int v = tid; v < (BM * K) / 4; v += 256) {
            int idx = v * 4;
            int row = idx / K, col = idx % K;
            int node = base + row;
            float4 val = make_float4(0.f, 0.f, 0.f, 0.f);
            if (node < NN)
                val = *reinterpret_cast<const float4*>(A + (size_t)node * K + col);
            *reinterpret_cast<float4*>(As + idx) = val;
        }
        __syncthreads();

        float4 acc[MPT];
#pragma unroll
        for (int m = 0; m < MPT; m++) acc[m] = make_float4(0.f, 0.f, 0.f, 0.f);
#pragma unroll 4
        for (int k = 0; k < K; k++) {
            float4 w = *reinterpret_cast<const float4*>(Ws + k * NOUT + 4 * tx);
#pragma unroll
            for (int m = 0; m < MPT; m++) {
                float a = As[(ty * MPT + m) * K + k];
                acc[m].x += a * w.x; acc[m].y += a * w.y;
                acc[m].z += a * w.z; acc[m].w += a * w.w;
            }
        }
#pragma unroll
        for (int m = 0; m < MPT; m++) {
            int node = base + ty * MPT + m;
            if (node < NN) {
                float4 o = make_float4(acc[m].x + bv.x, acc[m].y + bv.y,
                                       acc[m].z + bv.z, acc[m].w + bv.w);
                *reinterpret_cast<float4*>(out + (size_t)node * NOUT + 4 * tx) = o;
            }
        }
    }
}

// ---------------- layer-2 final: gather y, add z, L2norm, BN -> out ----------------
__global__ void k_final(const float* __restrict__ yz,
                        const float* __restrict__ gam, const float* __restrict__ bet,
                        const float* __restrict__ rm,  const float* __restrict__ rv,
                        float* __restrict__ out) {
    int w = (blockIdx.x * blockDim.x + threadIdx.x) >> 5;
    if (w >= NN) return;
    int lane = threadIdx.x & 31;
    int s = g_offs[w], e = g_offs[w + 1];
    float2 a0 = make_float2(0.f, 0.f), a1 = make_float2(0.f, 0.f);
    float2 a2 = make_float2(0.f, 0.f), a3 = make_float2(0.f, 0.f);
    int i = s;
    for (; i + 4 <= e; i += 4) {
        int s0 = __ldg(&g_src[i]),     s1 = __ldg(&g_src[i + 1]);
        int s2 = __ldg(&g_src[i + 2]), s3 = __ldg(&g_src[i + 3]);
        float2 v0 = *reinterpret_cast<const float2*>(yz + (size_t)s0 * 128 + 2 * lane);
        float2 v1 = *reinterpret_cast<const float2*>(yz + (size_t)s1 * 128 + 2 * lane);
        float2 v2 = *reinterpret_cast<const float2*>(yz + (size_t)s2 * 128 + 2 * lane);
        float2 v3 = *reinterpret_cast<const float2*>(yz + (size_t)s3 * 128 + 2 * lane);
        a0.x += v0.x; a0.y += v0.y;  a1.x += v1.x; a1.y += v1.y;
        a2.x += v2.x; a2.y += v2.y;  a3.x += v3.x; a3.y += v3.y;
    }
    for (; i < e; i++) {
        int sr = __ldg(&g_src[i]);
        float2 v = *reinterpret_cast<const float2*>(yz + (size_t)sr * 128 + 2 * lane);
        a0.x += v.x; a0.y += v.y;
    }
    float2 z = *reinterpret_cast<const float2*>(yz + (size_t)w * 128 + 64 + 2 * lane);
    float2 v;
    v.x = (a0.x + a1.x) + (a2.x + a3.x) + z.x;
    v.y = (a0.y + a1.y) + (a2.y + a3.y) + z.y;

    float ss = v.x * v.x + v.y * v.y;
#pragma unroll
    for (int o = 16; o > 0; o >>= 1) ss += __shfl_xor_sync(0xffffffffu, ss, o);
    float scale = 1.0f / fmaxf(sqrtf(ss), 1e-12f);

    float2 G  = *reinterpret_cast<const float2*>(gam + 2 * lane);
    float2 B  = *reinterpret_cast<const float2*>(bet + 2 * lane);
    float2 RM = *reinterpret_cast<const float2*>(rm  + 2 * lane);
    float2 RV = *reinterpret_cast<const float2*>(rv  + 2 * lane);
    float2 o;
    o.x = G.x * (v.x * scale - RM.x) * rsqrtf(RV.x + 1e-5f) + B.x;
    o.y = G.y * (v.y * scale - RM.y) * rsqrtf(RV.y + 1e-5f) + B.y;
    *reinterpret_cast<float2*>(out + (size_t)w * 64 + 2 * lane) = o;
}

// ---------------- launch ----------------
extern "C" void kernel_launch(void* const* d_in, const int* in_sizes, int n_in,
                              void* d_out, int out_size) {
    const float* x    = (const float*)d_in[0];
    const void*  ei   = d_in[1];
    const float* W1l  = (const float*)d_in[2];
    const float* b1   = (const float*)d_in[3];
    const float* W1r  = (const float*)d_in[4];
    const float* gam1 = (const float*)d_in[5];
    const float* bet1 = (const float*)d_in[6];
    const float* rm1  = (const float*)d_in[7];
    const float* rv1  = (const float*)d_in[8];
    const float* W2l  = (const float*)d_in[9];
    const float* b2   = (const float*)d_in[10];
    const float* W2r  = (const float*)d_in[11];
    const float* gam2 = (const float*)d_in[12];
    const float* bet2 = (const float*)d_in[13];
    const float* rm2  = (const float*)d_in[14];
    const float* rv2  = (const float*)d_in[15];
    float* out = (float*)d_out;

    float *agg1, *h, *yz;
    cudaGetSymbolAddress((void**)&agg1, g_agg1);
    cudaGetSymbolAddress((void**)&h,    g_h);
    cudaGetSymbolAddress((void**)&yz,   g_yz);

    constexpr int SMEM = (128 * 128 + 64 * 128) * 4;    // 96 KB
    cudaFuncSetAttribute(k_gemm1, cudaFuncAttributeMaxDynamicSharedMemorySize, SMEM);
    cudaFuncSetAttribute(k_gemm2, cudaFuncAttributeMaxDynamicSharedMemorySize, SMEM);

    const int NB = (NN + 1023) / 1024;
    const int EB = (EE + 255) / 256;
    const int WARP_BLOCKS = (NN * 32 + 255) / 256;

    // CSR build
    k_detect<<<1, 128>>>((const int*)ei);
    k_zero_cnt<<<(NN + 255) / 256, 256>>>();
    k_hist<<<EB, 256>>>(ei);
    k_scan1<<<NB, 1024>>>();
    k_scan2<<<1, 64>>>(NB);
    k_scan3<<<NB, 1024>>>();
    k_scatter<<<EB, 256>>>(ei);

    // layer 1: gather -> fused GEMM+norm+BN+ReLU
    k_agg1<<<WARP_BLOCKS, 256>>>(x, agg1);
    k_gemm1<<<296, 256, SMEM>>>(agg1, x, W1l, W1r, b1,
                                gam1, bet1, rm1, rv1, h);

    // layer 2: project -> gather+add+norm+BN
    k_gemm2<<<296, 256, SMEM>>>(h, W2l, W2r, b2, yz);
    k_final<<<WARP_BLOCKS, 256>>>(yz, gam2, bet2, rm2, rv2, out);
}

// round 3
// speedup vs baseline: 1.7011x; 1.3728x over previous
#include <cuda_runtime.h>
#include <cstdint>

#define NN   50000
#define EE   800000
#define DIN  64
#define DH   128
#define DOUT 64

#define WS_STRIDE 136
#define AS_STRIDE 132

// ---------------- scratch (static device globals; no allocation) ----------------
__device__ int   g_is64;
__device__ int   g_cnt[NN];
__device__ int   g_offs[NN + 1];
__device__ int   g_cursor[NN];
__device__ int   g_bsum[64];
__device__ int   g_boff[64];
__device__ int   g_src[EE];
__device__ float g_agg1[(size_t)NN * DIN];
__device__ float g_h   [(size_t)NN * DH];
__device__ float g_yz  [(size_t)NN * DH];

// ---------------- edge index helpers (int32 vs int64 detection) ----------------
__global__ void k_detect(const int* __restrict__ ei32) {
    __shared__ int nz;
    if (threadIdx.x == 0) nz = 0;
    __syncthreads();
    for (int i = threadIdx.x; i < 128; i += blockDim.x)
        if (ei32[2 * i + 1] != 0) atomicAdd(&nz, 1);
    __syncthreads();
    if (threadIdx.x == 0) g_is64 = (nz == 0) ? 1 : 0;
}

__device__ __forceinline__ int edge_val(const void* ei, int idx) {
    if (g_is64) return (int)((const long long*)ei)[idx];
    return ((const int*)ei)[idx];
}

// ---------------- CSR build ----------------
__global__ void k_zero_cnt() {
    int i = blockIdx.x * blockDim.x + threadIdx.x;
    if (i < NN) g_cnt[i] = 0;
}

__global__ void k_hist(const void* __restrict__ ei) {
    int e = blockIdx.x * blockDim.x + threadIdx.x;
    if (e < EE) {
        int d = edge_val(ei, EE + e);
        atomicAdd(&g_cnt[d], 1);
    }
}

__global__ void k_scan1() {
    __shared__ int s[1024];
    int t = threadIdx.x;
    int gid = blockIdx.x * 1024 + t;
    int v = (gid < NN) ? g_cnt[gid] : 0;
    s[t] = v;
    __syncthreads();
    for (int o = 1; o < 1024; o <<= 1) {
        int x = (t >= o) ? s[t - o] : 0;
        __syncthreads();
        s[t] += x;
        __syncthreads();
    }
    if (gid < NN) g_offs[gid + 1] = s[t];
    if (t == 1023) g_bsum[blockIdx.x] = s[1023];
}

__global__ void k_scan2(int nb) {
    __shared__ int s[64];
    int t = threadIdx.x;
    int v = (t < nb) ? g_bsum[t] : 0;
    s[t] = v;
    __syncthreads();
    for (int o = 1; o < 64; o <<= 1) {
        int x = (t >= o) ? s[t - o] : 0;
        __syncthreads();
        s[t] += x;
        __syncthreads();
    }
    g_boff[t] = s[t] - v;
}

__global__ void k_scan3() {
    int t = threadIdx.x;
    int gid = blockIdx.x * 1024 + t;
    if (gid < NN) {
        int f = g_offs[gid + 1] + g_boff[blockIdx.x];
        g_offs[gid + 1] = f;
        g_cursor[gid] = f - g_cnt[gid];
        if (gid == 0) g_offs[0] = 0;
    }
}

__global__ void k_scatter(const void* __restrict__ ei) {
    int e = blockIdx.x * blockDim.x + threadIdx.x;
    if (e < EE) {
        int s = edge_val(ei, e);
        int d = edge_val(ei, EE + e);
        int pos = atomicAdd(&g_cursor[d], 1);
        g_src[pos] = s;
    }
}

// ---------------- layer-1 aggregation: agg1 = segsum(x[src]), 64-d ----------------
__global__ void k_agg1(const float* __restrict__ feat, float* __restrict__ out) {
    int w = (blockIdx.x * blockDim.x + threadIdx.x) >> 5;
    if (w >= NN) return;
    int lane = threadIdx.x & 31;
    int s = g_offs[w], e = g_offs[w + 1];
    float2 a0 = make_float2(0.f, 0.f), a1 = make_float2(0.f, 0.f);
    float2 a2 = make_float2(0.f, 0.f), a3 = make_float2(0.f, 0.f);
    int i = s;
    for (; i + 4 <= e; i += 4) {
        int s0 = __ldg(&g_src[i]),     s1 = __ldg(&g_src[i + 1]);
        int s2 = __ldg(&g_src[i + 2]), s3 = __ldg(&g_src[i + 3]);
        float2 v0 = *reinterpret_cast<const float2*>(feat + (size_t)s0 * 64 + 2 * lane);
        float2 v1 = *reinterpret_cast<const float2*>(feat + (size_t)s1 * 64 + 2 * lane);
        float2 v2 = *reinterpret_cast<const float2*>(feat + (size_t)s2 * 64 + 2 * lane);
        float2 v3 = *reinterpret_cast<const float2*>(feat + (size_t)s3 * 64 + 2 * lane);
        a0.x += v0.x; a0.y += v0.y;  a1.x += v1.x; a1.y += v1.y;
        a2.x += v2.x; a2.y += v2.y;  a3.x += v3.x; a3.y += v3.y;
    }
    for (; i < e; i++) {
        int sr = __ldg(&g_src[i]);
        float2 v = *reinterpret_cast<const float2*>(feat + (size_t)sr * 64 + 2 * lane);
        a0.x += v.x; a0.y += v.y;
    }
    float2 acc = make_float2((a0.x + a1.x) + (a2.x + a3.x),
                             (a0.y + a1.y) + (a2.y + a3.y));
    *reinterpret_cast<float2*>(out + (size_t)w * 64 + 2 * lane) = acc;
}

// ---------------- tf32 helpers ----------------
__device__ __forceinline__ uint32_t f2tf(float f) {
    uint32_t u; asm("cvt.rna.tf32.f32 %0, %1;" : "=r"(u) : "f"(f)); return u;
}
__device__ __forceinline__ void mma_tf32(float4& d, const uint32_t* a, const uint32_t* b) {
    asm volatile("mma.sync.aligned.m16n8k8.row.col.f32.tf32.tf32.f32 "
        "{%0,%1,%2,%3}, {%4,%5,%6,%7}, {%8,%9}, {%0,%1,%2,%3};"
        : "+f"(d.x), "+f"(d.y), "+f"(d.z), "+f"(d.w)
        : "r"(a[0]), "r"(a[1]), "r"(a[2]), "r"(a[3]), "r"(b[0]), "r"(b[1]));
}

// ---------------- tensor-core dual GEMM, 64x128 tile, K=128 ----------------
// MODE 1: h = relu(bn(l2norm([agg1|x] @ [W1l;W1r] + b1)))       (A1=agg1, A2=x)
// MODE 2: yz = h @ [W2l | W2r], bias b2 on cols 64..127          (A1=h)
template <int MODE>
__global__ __launch_bounds__(256)
void k_tgemm(const float* __restrict__ A1, const float* __restrict__ A2,
             const float* __restrict__ Wl, const float* __restrict__ Wr,
             const float* __restrict__ bias,
             const float* __restrict__ gam, const float* __restrict__ bet,
             const float* __restrict__ rm,  const float* __restrict__ rv,
             float* __restrict__ out) {
    constexpr int BM = 64, K = 128, NOUT = 128;
    extern __shared__ uint32_t smu[];
    uint32_t* Ws = smu;                       // [K][WS_STRIDE] tf32 bits
    uint32_t* As = smu + K * WS_STRIDE;       // [BM][AS_STRIDE] tf32 bits
    float*    Cs = reinterpret_cast<float*>(As);

    const int tid  = threadIdx.x;
    const int lane = tid & 31, wid = tid >> 5;
    const int g = lane >> 2, t = lane & 3;
    const int wm = wid >> 2, wn = wid & 3;    // 2 (m) x 4 (n) warp grid

    // stage W as tf32 once per CTA
    for (int v = tid; v < K * NOUT / 4; v += 256) {
        int idx = v * 4, k = idx / NOUT, n = idx % NOUT;
        float4 w;
        if (MODE == 1) {
            if (k < 64) w = *reinterpret_cast<const float4*>(Wl + k * NOUT + n);
            else        w = *reinterpret_cast<const float4*>(Wr + (k - 64) * NOUT + n);
        } else {
            if (n < 64) w = *reinterpret_cast<const float4*>(Wl + k * 64 + n);
            else        w = *reinterpret_cast<const float4*>(Wr + k * 64 + (n - 64));
        }
        uint32_t* p = Ws + k * WS_STRIDE + n;
        p[0] = f2tf(w.x); p[1] = f2tf(w.y); p[2] = f2tf(w.z); p[3] = f2tf(w.w);
    }

    // per-lane epilogue params (column = 4*lane)
    float4 bv, G, Bb, RM, IS;
    if (MODE == 1) {
        bv = *reinterpret_cast<const float4*>(bias + 4 * lane);
        G  = *reinterpret_cast<const float4*>(gam  + 4 * lane);
        Bb = *reinterpret_cast<const float4*>(bet  + 4 * lane);
        RM = *reinterpret_cast<const float4*>(rm   + 4 * lane);
        float4 RV = *reinterpret_cast<const float4*>(rv + 4 * lane);
        IS.x = rsqrtf(RV.x + 1e-5f); IS.y = rsqrtf(RV.y + 1e-5f);
        IS.z = rsqrtf(RV.z + 1e-5f); IS.w = rsqrtf(RV.w + 1e-5f);
    } else {
        bv = make_float4(0.f, 0.f, 0.f, 0.f);
        if (4 * lane >= 64) bv = *reinterpret_cast<const float4*>(bias + 4 * lane - 64);
    }

    const int numTiles = (NN + BM - 1) / BM;
    for (int tile = blockIdx.x; tile < numTiles; tile += gridDim.x) {
        __syncthreads();
        const int base = tile * BM;

        // stage A tile as tf32
        for (int v = tid; v < BM * K / 4; v += 256) {
            int idx = v * 4, r = idx / K, c = idx % K;
            int node = base + r;
            float4 a = make_float4(0.f, 0.f, 0.f, 0.f);
            if (node < NN) {
                if (MODE == 1) {
                    if (c < 64) a = *reinterpret_cast<const float4*>(A1 + (size_t)node * 64 + c);
                    else        a = *reinterpret_cast<const float4*>(A2 + (size_t)node * 64 + (c - 64));
                } else {
                    a = *reinterpret_cast<const float4*>(A1 + (size_t)node * 128 + c);
                }
            }
            uint32_t* p = As + r * AS_STRIDE + c;
            p[0] = f2tf(a.x); p[1] = f2tf(a.y); p[2] = f2tf(a.z); p[3] = f2tf(a.w);
        }
        __syncthreads();

        float4 acc[2][4];
#pragma unroll
        for (int i = 0; i < 2; i++)
#pragma unroll
            for (int j = 0; j < 4; j++) acc[i][j] = make_float4(0.f, 0.f, 0.f, 0.f);

#pragma unroll 4
        for (int kk = 0; kk < 16; kk++) {
            const int cb = kk * 8;
            uint32_t a[2][4], b[4][2];
#pragma unroll
            for (int i = 0; i < 2; i++) {
                const uint32_t* ap = As + (wm * 32 + i * 16 + g) * AS_STRIDE + cb + t;
                a[i][0] = ap[0];
                a[i][1] = ap[8 * AS_STRIDE];
                a[i][2] = ap[4];
                a[i][3] = ap[8 * AS_STRIDE + 4];
            }
#pragma unroll
            for (int j = 0; j < 4; j++) {
                const uint32_t* bp = Ws + (cb + t) * WS_STRIDE + wn * 32 + j * 8 + g;
                b[j][0] = bp[0];
                b[j][1] = bp[4 * WS_STRIDE];
            }
#pragma unroll
            for (int i = 0; i < 2; i++)
#pragma unroll
                for (int j = 0; j < 4; j++) mma_tf32(acc[i][j], a[i], b[j]);
        }

        __syncthreads();   // mma reads of As done; reuse as C staging

#pragma unroll
        for (int i = 0; i < 2; i++)
#pragma unroll
            for (int j = 0; j < 4; j++) {
                int row = wm * 32 + i * 16 + g;
                int col = wn * 32 + j * 8 + 2 * t;
                Cs[row * AS_STRIDE + col]           = acc[i][j].x;
                Cs[row * AS_STRIDE + col + 1]       = acc[i][j].y;
                Cs[(row + 8) * AS_STRIDE + col]     = acc[i][j].z;
                Cs[(row + 8) * AS_STRIDE + col + 1] = acc[i][j].w;
            }
        __syncthreads();

        // epilogue: warp wid handles rows [wid*8, wid*8+8)
#pragma unroll
        for (int rr = 0; rr < 8; rr++) {
            int row = wid * 8 + rr;
            int node = base + row;
            float4 v = *reinterpret_cast<float4*>(Cs + row * AS_STRIDE + 4 * lane);
            v.x += bv.x; v.y += bv.y; v.z += bv.z; v.w += bv.w;
            if (MODE == 1) {
                float ss = v.x * v.x + v.y * v.y + v.z * v.z + v.w * v.w;
#pragma unroll
                for (int o = 16; o > 0; o >>= 1) ss += __shfl_xor_sync(0xffffffffu, ss, o);
                float sc = 1.0f / fmaxf(sqrtf(ss), 1e-12f);
                if (node < NN) {
                    float4 o;
                    o.x = fmaxf(G.x * (v.x * sc - RM.x) * IS.x + Bb.x, 0.f);
                    o.y = fmaxf(G.y * (v.y * sc - RM.y) * IS.y + Bb.y, 0.f);
                    o.z = fmaxf(G.z * (v.z * sc - RM.z) * IS.z + Bb.z, 0.f);
                    o.w = fmaxf(G.w * (v.w * sc - RM.w) * IS.w + Bb.w, 0.f);
                    *reinterpret_cast<float4*>(out + (size_t)node * NOUT + 4 * lane) = o;
                }
            } else {
                if (node < NN)
                    *reinterpret_cast<float4*>(out + (size_t)node * NOUT + 4 * lane) = v;
            }
        }
    }
}

// ---------------- layer-2 final: gather y, add z, L2norm, BN -> out ----------------
__global__ void k_final(const float* __restrict__ yz,
                        const float* __restrict__ gam, const float* __restrict__ bet,
                        const float* __restrict__ rm,  const float* __restrict__ rv,
                        float* __restrict__ out) {
    int w = (blockIdx.x * blockDim.x + threadIdx.x) >> 5;
    if (w >= NN) return;
    int lane = threadIdx.x & 31;
    int s = g_offs[w], e = g_offs[w + 1];
    float2 a0 = make_float2(0.f, 0.f), a1 = make_float2(0.f, 0.f);
    float2 a2 = make_float2(0.f, 0.f), a3 = make_float2(0.f, 0.f);
    int i = s;
    for (; i + 4 <= e; i += 4) {
        int s0 = __ldg(&g_src[i]),     s1 = __ldg(&g_src[i + 1]);
        int s2 = __ldg(&g_src[i + 2]), s3 = __ldg(&g_src[i + 3]);
        float2 v0 = *reinterpret_cast<const float2*>(yz + (size_t)s0 * 128 + 2 * lane);
        float2 v1 = *reinterpret_cast<const float2*>(yz + (size_t)s1 * 128 + 2 * lane);
        float2 v2 = *reinterpret_cast<const float2*>(yz + (size_t)s2 * 128 + 2 * lane);
        float2 v3 = *reinterpret_cast<const float2*>(yz + (size_t)s3 * 128 + 2 * lane);
        a0.x += v0.x; a0.y += v0.y;  a1.x += v1.x; a1.y += v1.y;
        a2.x += v2.x; a2.y += v2.y;  a3.x += v3.x; a3.y += v3.y;
    }
    for (; i < e; i++) {
        int sr = __ldg(&g_src[i]);
        float2 v = *reinterpret_cast<const float2*>(yz + (size_t)sr * 128 + 2 * lane);
        a0.x += v.x; a0.y += v.y;
    }
    float2 z = *reinterpret_cast<const float2*>(yz + (size_t)w * 128 + 64 + 2 * lane);
    float2 v;
    v.x = (a0.x + a1.x) + (a2.x + a3.x) + z.x;
    v.y = (a0.y + a1.y) + (a2.y + a3.y) + z.y;

    float ss = v.x * v.x + v.y * v.y;
#pragma unroll
    for (int o = 16; o > 0; o >>= 1) ss += __shfl_xor_sync(0xffffffffu, ss, o);
    float scale = 1.0f / fmaxf(sqrtf(ss), 1e-12f);

    float2 G  = *reinterpret_cast<const float2*>(gam + 2 * lane);
    float2 B  = *reinterpret_cast<const float2*>(bet + 2 * lane);
    float2 RM = *reinterpret_cast<const float2*>(rm  + 2 * lane);
    float2 RV = *reinterpret_cast<const float2*>(rv  + 2 * lane);
    float2 o;
    o.x = G.x * (v.x * scale - RM.x) * rsqrtf(RV.x + 1e-5f) + B.x;
    o.y = G.y * (v.y * scale - RM.y) * rsqrtf(RV.y + 1e-5f) + B.y;
    *reinterpret_cast<float2*>(out + (size_t)w * 64 + 2 * lane) = o;
}

// ---------------- launch ----------------
extern "C" void kernel_launch(void* const* d_in, const int* in_sizes, int n_in,
                              void* d_out, int out_size) {
    const float* x    = (const float*)d_in[0];
    const void*  ei   = d_in[1];
    const float* W1l  = (const float*)d_in[2];
    const float* b1   = (const float*)d_in[3];
    const float* W1r  = (const float*)d_in[4];
    const float* gam1 = (const float*)d_in[5];
    const float* bet1 = (const float*)d_in[6];
    const float* rm1  = (const float*)d_in[7];
    const float* rv1  = (const float*)d_in[8];
    const float* W2l  = (const float*)d_in[9];
    const float* b2   = (const float*)d_in[10];
    const float* W2r  = (const float*)d_in[11];
    const float* gam2 = (const float*)d_in[12];
    const float* bet2 = (const float*)d_in[13];
    const float* rm2  = (const float*)d_in[14];
    const float* rv2  = (const float*)d_in[15];
    float* out = (float*)d_out;

    float *agg1, *h, *yz;
    cudaGetSymbolAddress((void**)&agg1, g_agg1);
    cudaGetSymbolAddress((void**)&h,    g_h);
    cudaGetSymbolAddress((void**)&yz,   g_yz);

    constexpr int SMEM = (128 * WS_STRIDE + 64 * AS_STRIDE) * 4;   // 103,424 B
    cudaFuncSetAttribute(k_tgemm<1>, cudaFuncAttributeMaxDynamicSharedMemorySize, SMEM);
    cudaFuncSetAttribute(k_tgemm<2>, cudaFuncAttributeMaxDynamicSharedMemorySize, SMEM);

    const int NB = (NN + 1023) / 1024;
    const int EB = (EE + 255) / 256;
    const int WARP_BLOCKS = (NN * 32 + 255) / 256;

    // CSR build
    k_detect<<<1, 128>>>((const int*)ei);
    k_zero_cnt<<<(NN + 255) / 256, 256>>>();
    k_hist<<<EB, 256>>>(ei);
    k_scan1<<<NB, 1024>>>();
    k_scan2<<<1, 64>>>(NB);
    k_scan3<<<NB, 1024>>>();
    k_scatter<<<EB, 256>>>(ei);

    // layer 1: gather -> tensor GEMM + fused norm/BN/ReLU
    k_agg1<<<WARP_BLOCKS, 256>>>(x, agg1);
    k_tgemm<1><<<296, 256, SMEM>>>(agg1, x, W1l, W1r, b1,
                                   gam1, bet1, rm1, rv1, h);

    // layer 2: tensor projection GEMM -> gather+add+norm+BN
    k_tgemm<2><<<296, 256, SMEM>>>(h, nullptr, W2l, W2r, b2,
                                   nullptr, nullptr, nullptr, nullptr, yz);
    k_final<<<WARP_BLOCKS, 256>>>(yz, gam2, bet2, rm2, rv2, out);
}